// round 4
// baseline (speedup 1.0000x reference)
#include <cuda_runtime.h>
#include <math.h>

#define N_TOK 8192
#define D_DIM 1024
#define TIME_DECAY_F 86400.0f
#define EPS_F 1e-10f
#define SCALE_INV (1.0f / 32.0f)   // 1/sqrt(1024)

// ---- scratch (no allocations allowed) ----
__device__ float g_Q[(size_t)N_TOK * D_DIM];
__device__ float g_K[(size_t)N_TOK * D_DIM];
__device__ float g_V[(size_t)N_TOK * D_DIM];
__device__ float g_S[(size_t)N_TOK * N_TOK];

// ============================================================
// GEMM NT: C[M,Nc] = A[M,K] @ B[Nc,K]^T  (both row-major)
// MODE 0: epilogue adds bias[n]          (QKV projections)
// MODE 1: epilogue acc/32 + log(exp(-|ti-tj|/TD)+eps)  (scores)
// Tiles: BM=BN=128, BK=8, 256 threads, 8x8 per thread.
// ============================================================
template <int MODE>
__global__ __launch_bounds__(256)
void gemm_nt(const float* __restrict__ A,
             const float* __restrict__ B,
             const float* __restrict__ aux,   // bias[Nc] (MODE 0) or timestamps[] (MODE 1)
             float* __restrict__ C,
             int M, int Nc, int K)
{
    __shared__ float As[8][128];
    __shared__ float Bs[8][128];

    const int tid = threadIdx.x;
    const int tx = tid & 15;          // 0..15
    const int ty = tid >> 4;          // 0..15
    const int bm = blockIdx.y * 128;
    const int bn = blockIdx.x * 128;

    const int ldRow = tid >> 1;       // 0..127
    const int ldCol = (tid & 1) * 4;  // 0 or 4

    const float* Aptr = A + (size_t)(bm + ldRow) * K + ldCol;
    const float* Bptr = B + (size_t)(bn + ldRow) * K + ldCol;

    float acc[8][8];
#pragma unroll
    for (int i = 0; i < 8; i++)
#pragma unroll
        for (int j = 0; j < 8; j++) acc[i][j] = 0.0f;

    for (int k0 = 0; k0 < K; k0 += 8) {
        float4 a4 = *(const float4*)(Aptr + k0);
        float4 b4 = *(const float4*)(Bptr + k0);
        As[ldCol + 0][ldRow] = a4.x;
        As[ldCol + 1][ldRow] = a4.y;
        As[ldCol + 2][ldRow] = a4.z;
        As[ldCol + 3][ldRow] = a4.w;
        Bs[ldCol + 0][ldRow] = b4.x;
        Bs[ldCol + 1][ldRow] = b4.y;
        Bs[ldCol + 2][ldRow] = b4.z;
        Bs[ldCol + 3][ldRow] = b4.w;
        __syncthreads();

#pragma unroll
        for (int k = 0; k < 8; k++) {
            float ra[8], rb[8];
#pragma unroll
            for (int i = 0; i < 8; i++) ra[i] = As[k][ty * 8 + i];
#pragma unroll
            for (int j = 0; j < 8; j++) rb[j] = Bs[k][tx * 8 + j];
#pragma unroll
            for (int i = 0; i < 8; i++)
#pragma unroll
                for (int j = 0; j < 8; j++)
                    acc[i][j] = fmaf(ra[i], rb[j], acc[i][j]);
        }
        __syncthreads();
    }

    if (MODE == 0) {
        // C = acc + bias[n]
        float bb[8];
#pragma unroll
        for (int j = 0; j < 8; j++) bb[j] = aux[bn + tx * 8 + j];
#pragma unroll
        for (int i = 0; i < 8; i++) {
            size_t rowoff = (size_t)(bm + ty * 8 + i) * Nc + bn + tx * 8;
#pragma unroll
            for (int j = 0; j < 8; j++)
                C[rowoff + j] = acc[i][j] + bb[j];
        }
    } else {
        // scores epilogue: acc/32 + log(exp(-|ti - tj|/TD) + eps)
        float ti[8], tj[8];
#pragma unroll
        for (int i = 0; i < 8; i++) ti[i] = aux[bm + ty * 8 + i];
#pragma unroll
        for (int j = 0; j < 8; j++) tj[j] = aux[bn + tx * 8 + j];
#pragma unroll
        for (int i = 0; i < 8; i++) {
            size_t rowoff = (size_t)(bm + ty * 8 + i) * Nc + bn + tx * 8;
#pragma unroll
            for (int j = 0; j < 8; j++) {
                float a = fabsf(ti[i] - tj[j]) * (1.0f / TIME_DECAY_F);
                float bias = logf(expf(-a) + EPS_F);
                C[rowoff + j] = acc[i][j] * SCALE_INV + bias;
            }
        }
    }
}

// ============================================================
// GEMM NN: C[M,Nc] = A[M,K] @ B[K,Nc]   (row-major)
// Used for O = P @ V  (M=8192, K=8192, Nc=1024)
// ============================================================
__global__ __launch_bounds__(256)
void gemm_nn(const float* __restrict__ A,
             const float* __restrict__ B,
             float* __restrict__ C,
             int M, int Nc, int K)
{
    __shared__ float As[8][128];
    __shared__ float Bs[8][128];

    const int tid = threadIdx.x;
    const int tx = tid & 15;
    const int ty = tid >> 4;
    const int bm = blockIdx.y * 128;
    const int bn = blockIdx.x * 128;

    const int aRow = tid >> 1;
    const int aCol = (tid & 1) * 4;
    const int bRow = tid >> 5;           // 0..7
    const int bCol = (tid & 31) * 4;     // 0..124

    const float* Aptr = A + (size_t)(bm + aRow) * K + aCol;

    float acc[8][8];
#pragma unroll
    for (int i = 0; i < 8; i++)
#pragma unroll
        for (int j = 0; j < 8; j++) acc[i][j] = 0.0f;

    for (int k0 = 0; k0 < K; k0 += 8) {
        float4 a4 = *(const float4*)(Aptr + k0);
        float4 b4 = *(const float4*)(B + (size_t)(k0 + bRow) * Nc + bn + bCol);
        As[aCol + 0][aRow] = a4.x;
        As[aCol + 1][aRow] = a4.y;
        As[aCol + 2][aRow] = a4.z;
        As[aCol + 3][aRow] = a4.w;
        *(float4*)&Bs[bRow][bCol] = b4;
        __syncthreads();

#pragma unroll
        for (int k = 0; k < 8; k++) {
            float ra[8], rb[8];
#pragma unroll
            for (int i = 0; i < 8; i++) ra[i] = As[k][ty * 8 + i];
#pragma unroll
            for (int j = 0; j < 8; j++) rb[j] = Bs[k][tx * 8 + j];
#pragma unroll
            for (int i = 0; i < 8; i++)
#pragma unroll
                for (int j = 0; j < 8; j++)
                    acc[i][j] = fmaf(ra[i], rb[j], acc[i][j]);
        }
        __syncthreads();
    }

#pragma unroll
    for (int i = 0; i < 8; i++) {
        size_t rowoff = (size_t)(bm + ty * 8 + i) * Nc + bn + tx * 8;
#pragma unroll
        for (int j = 0; j < 8; j++)
            C[rowoff + j] = acc[i][j];
    }
}

// ============================================================
// Row softmax over g_S: one block per row, 256 threads,
// 32 elements/thread held in registers (N=8192).
// ============================================================
__global__ __launch_bounds__(256)
void softmax_rows(float* __restrict__ S, int n)
{
    const int row = blockIdx.x;
    float* p = S + (size_t)row * n;
    const int tid = threadIdx.x;

    float v[32];
    float m = -INFINITY;
#pragma unroll
    for (int i = 0; i < 32; i++) {
        v[i] = p[tid + i * 256];
        m = fmaxf(m, v[i]);
    }

    __shared__ float red[256];
    red[tid] = m;
    __syncthreads();
    for (int s = 128; s > 0; s >>= 1) {
        if (tid < s) red[tid] = fmaxf(red[tid], red[tid + s]);
        __syncthreads();
    }
    m = red[0];
    __syncthreads();

    float sum = 0.0f;
#pragma unroll
    for (int i = 0; i < 32; i++) {
        v[i] = expf(v[i] - m);
        sum += v[i];
    }
    red[tid] = sum;
    __syncthreads();
    for (int s = 128; s > 0; s >>= 1) {
        if (tid < s) red[tid] += red[tid + s];
        __syncthreads();
    }
    float inv = 1.0f / red[0];
    __syncthreads();

#pragma unroll
    for (int i = 0; i < 32; i++)
        p[tid + i * 256] = v[i] * inv;
}

// ============================================================
// kernel_launch
// inputs: 0:x [N,D] 1:timestamps [N] 2:Wq [D,D] 3:bq [D]
//         4:Wk 5:bk 6:Wv 7:bv      output: [N,D] fp32
// ============================================================
extern "C" void kernel_launch(void* const* d_in, const int* in_sizes, int n_in,
                              void* d_out, int out_size)
{
    const float* x  = (const float*)d_in[0];
    const float* ts = (const float*)d_in[1];
    const float* Wq = (const float*)d_in[2];
    const float* bq = (const float*)d_in[3];
    const float* Wk = (const float*)d_in[4];
    const float* bk = (const float*)d_in[5];
    const float* Wv = (const float*)d_in[6];
    const float* bv = (const float*)d_in[7];
    float* out = (float*)d_out;

    float *Qp, *Kp, *Vp, *Sp;
    cudaGetSymbolAddress((void**)&Qp, g_Q);
    cudaGetSymbolAddress((void**)&Kp, g_K);
    cudaGetSymbolAddress((void**)&Vp, g_V);
    cudaGetSymbolAddress((void**)&Sp, g_S);

    dim3 thr(256);

    // QKV projections: [8192,1024] = x[8192,1024] @ W^T + b
    {
        dim3 grid(D_DIM / 128, N_TOK / 128);   // (8, 64)
        gemm_nt<0><<<grid, thr>>>(x, Wq, bq, Qp, N_TOK, D_DIM, D_DIM);
        gemm_nt<0><<<grid, thr>>>(x, Wk, bk, Kp, N_TOK, D_DIM, D_DIM);
        gemm_nt<0><<<grid, thr>>>(x, Wv, bv, Vp, N_TOK, D_DIM, D_DIM);
    }

    // Scores: S = Q @ K^T / 32 + temporal bias
    {
        dim3 grid(N_TOK / 128, N_TOK / 128);   // (64, 64)
        gemm_nt<1><<<grid, thr>>>(Qp, Kp, ts, Sp, N_TOK, N_TOK, D_DIM);
    }

    // Softmax per row
    softmax_rows<<<N_TOK, thr>>>(Sp, N_TOK);

    // O = P @ V
    {
        dim3 grid(D_DIM / 128, N_TOK / 128);   // (8, 64)
        gemm_nn<<<grid, thr>>>(Sp, Vp, out, N_TOK, D_DIM, N_TOK);
    }
}

// round 5
// speedup vs baseline: 2.0048x; 2.0048x over previous
#include <cuda_runtime.h>
#include <cuda_bf16.h>
#include <math.h>
#include <stdint.h>

#define N_TOK 8192
#define D_DIM 1024
#define TD_INV (1.0f / 86400.0f)
#define EPS_F 1e-10f
#define SCALE_INV (1.0f / 32.0f)   // 1/sqrt(1024)

// ---------------- scratch (no allocations allowed) ----------------
__device__ __nv_bfloat16 g_Xh[(size_t)N_TOK * D_DIM];
__device__ __nv_bfloat16 g_Xl[(size_t)N_TOK * D_DIM];
__device__ __nv_bfloat16 g_Wh[(size_t)D_DIM * D_DIM];
__device__ __nv_bfloat16 g_Wl[(size_t)D_DIM * D_DIM];
__device__ __nv_bfloat16 g_Qh[(size_t)N_TOK * D_DIM];
__device__ __nv_bfloat16 g_Ql[(size_t)N_TOK * D_DIM];
__device__ __nv_bfloat16 g_Kh[(size_t)N_TOK * D_DIM];
__device__ __nv_bfloat16 g_Kl[(size_t)N_TOK * D_DIM];
__device__ __nv_bfloat16 g_Vth[(size_t)D_DIM * N_TOK];  // V transposed [D][N]
__device__ __nv_bfloat16 g_Vtl[(size_t)D_DIM * N_TOK];
__device__ float         g_S [(size_t)N_TOK * N_TOK];
__device__ __nv_bfloat16 g_Ph[(size_t)N_TOK * N_TOK];
__device__ __nv_bfloat16 g_Pl[(size_t)N_TOK * N_TOK];

// ---------------- PTX helpers ----------------
__device__ __forceinline__ void cp_async16(uint32_t s, const void* g) {
    asm volatile("cp.async.cg.shared.global [%0], [%1], 16;\n" :: "r"(s), "l"(g));
}
__device__ __forceinline__ void ldsm4(uint32_t* r, uint32_t a) {
    asm volatile("ldmatrix.sync.aligned.m8n8.x4.shared.b16 {%0,%1,%2,%3}, [%4];\n"
                 : "=r"(r[0]), "=r"(r[1]), "=r"(r[2]), "=r"(r[3]) : "r"(a));
}
__device__ __forceinline__ void mma16816(float* c, const uint32_t* a, const uint32_t* b) {
    asm volatile("mma.sync.aligned.m16n8k16.row.col.f32.bf16.bf16.f32 "
                 "{%0,%1,%2,%3}, {%4,%5,%6,%7}, {%8,%9}, {%0,%1,%2,%3};\n"
                 : "+f"(c[0]), "+f"(c[1]), "+f"(c[2]), "+f"(c[3])
                 : "r"(a[0]), "r"(a[1]), "r"(a[2]), "r"(a[3]), "r"(b[0]), "r"(b[1]));
}

// ============================================================
// Split fp32 -> (hi, lo) bf16
// ============================================================
__global__ __launch_bounds__(256)
void split_f32(const float* __restrict__ src,
               __nv_bfloat16* __restrict__ hi,
               __nv_bfloat16* __restrict__ lo, int n)
{
    int i = blockIdx.x * 256 + threadIdx.x;
    if (i < n) {
        float v = src[i];
        __nv_bfloat16 h = __float2bfloat16(v);
        hi[i] = h;
        lo[i] = __float2bfloat16(v - __bfloat162float(h));
    }
}

// ============================================================
// Tensor-core NT GEMM with bf16 split precision (3 passes).
// C[M,Nc] = (Ahi+Alo)[M,K] @ (Bhi+Blo)[Nc,K]^T   (row-major)
// BM=BN=128, BK=16, 256 threads (8 warps: 4(m) x 2(n), warp tile 32x64).
// MODE 0: +bias[n], store split bf16 row-major (Q/K projections)
// MODE 1: *1/32 + temporal bias, store fp32 (scores)
// MODE 2: +bias[n], store split bf16 TRANSPOSED [Nc][M] (V projection)
// MODE 3: plain fp32 store (output)
// ============================================================
#define PADK 24
#define MATB (128 * PADK * 2)   // 6144 bytes per matrix per stage
#define STAGEB (4 * MATB)       // 24576 bytes per stage

template <int MODE>
__global__ __launch_bounds__(256)
void gemm_nt_tc(const __nv_bfloat16* __restrict__ Ahi, const __nv_bfloat16* __restrict__ Alo,
                const __nv_bfloat16* __restrict__ Bhi, const __nv_bfloat16* __restrict__ Blo,
                const float* __restrict__ aux,        // bias[Nc] or timestamps[]
                float* __restrict__ Cf,
                __nv_bfloat16* __restrict__ Chi, __nv_bfloat16* __restrict__ Clo,
                int M, int Nc, int K)
{
    __shared__ __align__(16) __nv_bfloat16 smem[2][4][128][PADK];

    const int tid  = threadIdx.x;
    const int lane = tid & 31;
    const int wid  = tid >> 5;
    const int wm   = wid >> 1;          // 0..3 -> m offset wm*32
    const int wn   = wid & 1;           // 0..1 -> n offset wn*64
    const int bm   = blockIdx.y * 128;
    const int bn   = blockIdx.x * 128;

    // cp.async load mapping: thread -> (row, 8-elem half)
    const int ldRow = tid >> 1;          // 0..127
    const int ldCol = (tid & 1) * 8;     // 0 or 8 (bf16 elems)

    const __nv_bfloat16* gAh = Ahi + (size_t)(bm + ldRow) * K + ldCol;
    const __nv_bfloat16* gAl = Alo + (size_t)(bm + ldRow) * K + ldCol;
    const __nv_bfloat16* gBh = Bhi + (size_t)(bn + ldRow) * K + ldCol;
    const __nv_bfloat16* gBl = Blo + (size_t)(bn + ldRow) * K + ldCol;

    const uint32_t sbase  = (uint32_t)__cvta_generic_to_shared(&smem[0][0][0][0]);
    const uint32_t sStore = sbase + (ldRow * PADK + ldCol) * 2;

    // ldmatrix addressing
    const int l8  = lane & 7;
    const int sub = lane >> 3;
    const uint32_t aOff = sbase + 0 * MATB +
        ((wm * 32 + l8 + (sub & 1) * 8) * PADK + (sub >> 1) * 8) * 2;
    const uint32_t bOff = sbase + 2 * MATB +
        ((wn * 64 + l8 + (sub >> 1) * 8) * PADK + (sub & 1) * 8) * 2;

    float acc[2][8][4];
#pragma unroll
    for (int i = 0; i < 2; i++)
#pragma unroll
        for (int j = 0; j < 8; j++)
#pragma unroll
            for (int r = 0; r < 4; r++) acc[i][j][r] = 0.0f;

    const int nIter = K >> 4;

    // prefetch stage 0
    cp_async16(sStore + 0 * MATB, gAh);
    cp_async16(sStore + 1 * MATB, gAl);
    cp_async16(sStore + 2 * MATB, gBh);
    cp_async16(sStore + 3 * MATB, gBl);
    asm volatile("cp.async.commit_group;\n");

    for (int it = 0; it < nIter; ++it) {
        const uint32_t curS = (uint32_t)(it & 1) * STAGEB;
        if (it + 1 < nIter) {
            const int k = (it + 1) << 4;
            const uint32_t st = (uint32_t)((it + 1) & 1) * STAGEB + sStore;
            cp_async16(st + 0 * MATB, gAh + k);
            cp_async16(st + 1 * MATB, gAl + k);
            cp_async16(st + 2 * MATB, gBh + k);
            cp_async16(st + 3 * MATB, gBl + k);
            asm volatile("cp.async.commit_group;\n");
            asm volatile("cp.async.wait_group 1;\n");
        } else {
            asm volatile("cp.async.wait_group 0;\n");
        }
        __syncthreads();

        uint32_t Af[2][2][4];   // [hi/lo][m-tile][reg]
        uint32_t Bf[2][4][4];   // [hi/lo][n16-chunk][reg]
#pragma unroll
        for (int i = 0; i < 2; i++) {
            ldsm4(Af[0][i], curS + aOff +        i * 16 * PADK * 2);
            ldsm4(Af[1][i], curS + aOff + MATB + i * 16 * PADK * 2);
        }
#pragma unroll
        for (int jj = 0; jj < 4; jj++) {
            ldsm4(Bf[0][jj], curS + bOff +        jj * 16 * PADK * 2);
            ldsm4(Bf[1][jj], curS + bOff + MATB + jj * 16 * PADK * 2);
        }

#pragma unroll
        for (int i = 0; i < 2; i++)
#pragma unroll
            for (int j = 0; j < 8; j++) {
                const uint32_t* bh = &Bf[0][j >> 1][(j & 1) * 2];
                const uint32_t* bl = &Bf[1][j >> 1][(j & 1) * 2];
                mma16816(acc[i][j], Af[0][i], bh);   // hi*hi
                mma16816(acc[i][j], Af[1][i], bh);   // lo*hi
                mma16816(acc[i][j], Af[0][i], bl);   // hi*lo
            }
        __syncthreads();
    }

    // ---------------- epilogue ----------------
    const int rBase = bm + wm * 32 + (lane >> 2);
    const int cBase = bn + wn * 64 + (lane & 3) * 2;

    if (MODE == 0 || MODE == 2) {
        float bb[8][2];
#pragma unroll
        for (int j = 0; j < 8; j++) {
            bb[j][0] = aux[cBase + j * 8];
            bb[j][1] = aux[cBase + j * 8 + 1];
        }
#pragma unroll
        for (int i = 0; i < 2; i++)
#pragma unroll
            for (int h = 0; h < 2; h++) {
                const int r = rBase + i * 16 + h * 8;
#pragma unroll
                for (int j = 0; j < 8; j++) {
                    const int c = cBase + j * 8;
                    float v0 = acc[i][j][h * 2 + 0] + bb[j][0];
                    float v1 = acc[i][j][h * 2 + 1] + bb[j][1];
                    __nv_bfloat16 h0 = __float2bfloat16(v0);
                    __nv_bfloat16 h1 = __float2bfloat16(v1);
                    __nv_bfloat16 l0 = __float2bfloat16(v0 - __bfloat162float(h0));
                    __nv_bfloat16 l1 = __float2bfloat16(v1 - __bfloat162float(h1));
                    if (MODE == 0) {
                        size_t o = (size_t)r * Nc + c;
                        __nv_bfloat162 hv; hv.x = h0; hv.y = h1;
                        __nv_bfloat162 lv; lv.x = l0; lv.y = l1;
                        *reinterpret_cast<__nv_bfloat162*>(Chi + o) = hv;
                        *reinterpret_cast<__nv_bfloat162*>(Clo + o) = lv;
                    } else {
                        Chi[(size_t)c * M + r]       = h0;
                        Chi[(size_t)(c + 1) * M + r] = h1;
                        Clo[(size_t)c * M + r]       = l0;
                        Clo[(size_t)(c + 1) * M + r] = l1;
                    }
                }
            }
    } else if (MODE == 1) {
        float tj[8][2];
#pragma unroll
        for (int j = 0; j < 8; j++) {
            tj[j][0] = aux[cBase + j * 8];
            tj[j][1] = aux[cBase + j * 8 + 1];
        }
#pragma unroll
        for (int i = 0; i < 2; i++)
#pragma unroll
            for (int h = 0; h < 2; h++) {
                const int r = rBase + i * 16 + h * 8;
                const float tr = aux[r];
#pragma unroll
                for (int j = 0; j < 8; j++) {
                    const int c = cBase + j * 8;
                    // log(exp(-a)+eps) == -a + log1p(eps*e^a) ~= -a + eps*e^a  (a<=10)
                    float a0 = fabsf(tr - tj[j][0]) * TD_INV;
                    float a1 = fabsf(tr - tj[j][1]) * TD_INV;
                    float b0 = EPS_F * __expf(a0) - a0;
                    float b1 = EPS_F * __expf(a1) - a1;
                    float2 v;
                    v.x = acc[i][j][h * 2 + 0] * SCALE_INV + b0;
                    v.y = acc[i][j][h * 2 + 1] * SCALE_INV + b1;
                    *reinterpret_cast<float2*>(Cf + (size_t)r * Nc + c) = v;
                }
            }
    } else {  // MODE 3: plain fp32
#pragma unroll
        for (int i = 0; i < 2; i++)
#pragma unroll
            for (int h = 0; h < 2; h++) {
                const int r = rBase + i * 16 + h * 8;
#pragma unroll
                for (int j = 0; j < 8; j++) {
                    const int c = cBase + j * 8;
                    float2 v;
                    v.x = acc[i][j][h * 2 + 0];
                    v.y = acc[i][j][h * 2 + 1];
                    *reinterpret_cast<float2*>(Cf + (size_t)r * Nc + c) = v;
                }
            }
    }
}

// ============================================================
// Row softmax: one block per row, 256 threads, 32 elems/thread.
// Reads fp32 S, writes split bf16 P (hi, lo).
// ============================================================
__global__ __launch_bounds__(256)
void softmax_split(const float* __restrict__ S,
                   __nv_bfloat16* __restrict__ Ph,
                   __nv_bfloat16* __restrict__ Pl, int n)
{
    const int row = blockIdx.x;
    const float* p = S + (size_t)row * n;
    const int tid = threadIdx.x;

    float v[32];
    float m = -INFINITY;
#pragma unroll
    for (int i = 0; i < 32; i++) {
        v[i] = p[tid + i * 256];
        m = fmaxf(m, v[i]);
    }

    __shared__ float red[256];
    red[tid] = m;
    __syncthreads();
    for (int s = 128; s > 0; s >>= 1) {
        if (tid < s) red[tid] = fmaxf(red[tid], red[tid + s]);
        __syncthreads();
    }
    m = red[0];
    __syncthreads();

    float sum = 0.0f;
#pragma unroll
    for (int i = 0; i < 32; i++) {
        v[i] = __expf(v[i] - m);
        sum += v[i];
    }
    red[tid] = sum;
    __syncthreads();
    for (int s = 128; s > 0; s >>= 1) {
        if (tid < s) red[tid] += red[tid + s];
        __syncthreads();
    }
    const float inv = 1.0f / red[0];
    __syncthreads();

    size_t base = (size_t)row * n + tid;
#pragma unroll
    for (int i = 0; i < 32; i++) {
        float pv = v[i] * inv;
        __nv_bfloat16 h = __float2bfloat16(pv);
        Ph[base + i * 256] = h;
        Pl[base + i * 256] = __float2bfloat16(pv - __bfloat162float(h));
    }
}

// ============================================================
// kernel_launch
// inputs: 0:x [N,D] 1:timestamps [N] 2:Wq [D,D] 3:bq [D]
//         4:Wk 5:bk 6:Wv 7:bv      output: [N,D] fp32
// ============================================================
extern "C" void kernel_launch(void* const* d_in, const int* in_sizes, int n_in,
                              void* d_out, int out_size)
{
    const float* x  = (const float*)d_in[0];
    const float* ts = (const float*)d_in[1];
    const float* Wq = (const float*)d_in[2];
    const float* bq = (const float*)d_in[3];
    const float* Wk = (const float*)d_in[4];
    const float* bk = (const float*)d_in[5];
    const float* Wv = (const float*)d_in[6];
    const float* bv = (const float*)d_in[7];
    float* out = (float*)d_out;

    __nv_bfloat16 *Xh, *Xl, *Wh, *Wl, *Qh, *Ql, *Kh, *Kl, *Vth, *Vtl, *Ph, *Pl;
    float* Sp;
    cudaGetSymbolAddress((void**)&Xh, g_Xh);  cudaGetSymbolAddress((void**)&Xl, g_Xl);
    cudaGetSymbolAddress((void**)&Wh, g_Wh);  cudaGetSymbolAddress((void**)&Wl, g_Wl);
    cudaGetSymbolAddress((void**)&Qh, g_Qh);  cudaGetSymbolAddress((void**)&Ql, g_Ql);
    cudaGetSymbolAddress((void**)&Kh, g_Kh);  cudaGetSymbolAddress((void**)&Kl, g_Kl);
    cudaGetSymbolAddress((void**)&Vth, g_Vth); cudaGetSymbolAddress((void**)&Vtl, g_Vtl);
    cudaGetSymbolAddress((void**)&Ph, g_Ph);  cudaGetSymbolAddress((void**)&Pl, g_Pl);
    cudaGetSymbolAddress((void**)&Sp, g_S);

    const dim3 thr(256);
    const int nXD = N_TOK * D_DIM;
    const int nWW = D_DIM * D_DIM;

    // split x
    split_f32<<<nXD / 256, thr>>>(x, Xh, Xl, nXD);

    // QKV projections (W buffer reused sequentially in-stream)
    const dim3 gProj(D_DIM / 128, N_TOK / 128);
    split_f32<<<nWW / 256, thr>>>(Wq, Wh, Wl, nWW);
    gemm_nt_tc<0><<<gProj, thr>>>(Xh, Xl, Wh, Wl, bq, nullptr, Qh, Ql,
                                  N_TOK, D_DIM, D_DIM);
    split_f32<<<nWW / 256, thr>>>(Wk, Wh, Wl, nWW);
    gemm_nt_tc<0><<<gProj, thr>>>(Xh, Xl, Wh, Wl, bk, nullptr, Kh, Kl,
                                  N_TOK, D_DIM, D_DIM);
    split_f32<<<nWW / 256, thr>>>(Wv, Wh, Wl, nWW);
    gemm_nt_tc<2><<<gProj, thr>>>(Xh, Xl, Wh, Wl, bv, nullptr, Vth, Vtl,
                                  N_TOK, D_DIM, D_DIM);

    // Scores: S = QK^T/32 + temporal bias
    const dim3 gScore(N_TOK / 128, N_TOK / 128);
    gemm_nt_tc<1><<<gScore, thr>>>(Qh, Ql, Kh, Kl, ts, Sp, nullptr, nullptr,
                                   N_TOK, N_TOK, D_DIM);

    // Softmax -> split P
    softmax_split<<<N_TOK, thr>>>(Sp, Ph, Pl, N_TOK);

    // O = P @ Vt^T
    const dim3 gOut(D_DIM / 128, N_TOK / 128);
    gemm_nt_tc<3><<<gOut, thr>>>(Ph, Pl, Vth, Vtl, nullptr, out, nullptr, nullptr,
                                 N_TOK, D_DIM, N_TOK);
}